// round 16
// baseline (speedup 1.0000x reference)
#include <cuda_runtime.h>
#include <cuda_fp16.h>
#include <cstdint>

#define Bc 8
#define Sc 1024
#define Dc 1024
#define Hc 16
#define DKc 64

// ---------------- scratch (static device globals; no allocation) -------------
__device__ __half g_A16[3u * 8192u * 1024u];        // fp16 inQ/inK/inV
__device__ __half g_Q16[(size_t)Bc * Hc * Sc * DKc];  // [b,h,s,dk] fp16
__device__ __half g_K16[(size_t)Bc * Hc * Sc * DKc];
__device__ __half g_V16[(size_t)Bc * Hc * Sc * DKc];
__device__ __half g_ctx16[(size_t)Bc * Sc * Dc];    // [m][1024] fp16
__device__ float  g_fc[(size_t)Bc * Sc * Dc];
__device__ __half g_Wt16[4u * 1024u * 1024u];       // transposed fp16 [n][k]
__device__ float  g_rsp[128u * 8u * 1024u];         // row-sum partials [bh][kt][q]
__device__ __half g_P16[(size_t)128u * 1024u * 1024u]; // unnormalized exp scores

// ======================= helpers =============================================
__device__ __forceinline__ uint32_t smem_u32(const void* p) {
    uint32_t a;
    asm("{ .reg .u64 t; cvta.to.shared.u64 t, %1; cvt.u32.u64 %0, t; }"
        : "=r"(a) : "l"(p));
    return a;
}

__device__ __forceinline__ void cp16(uint32_t s, const void* g) {
    asm volatile("cp.async.cg.shared.global [%0], [%1], 16;"
                 :: "r"(s), "l"(g) : "memory");
}

__device__ __forceinline__ uint32_t h2u(__half2 h) {
    return *reinterpret_cast<uint32_t*>(&h);
}

// mma.sync m16n8k16 fp16->fp32 (base sm_80+ ISA)
__device__ __forceinline__ void mma_f16(float* c, const uint32_t* a,
                                        const uint32_t* b) {
    asm volatile(
        "mma.sync.aligned.m16n8k16.row.col.f32.f16.f16.f32 "
        "{%0,%1,%2,%3}, {%4,%5,%6,%7}, {%8,%9}, {%0,%1,%2,%3};"
        : "+f"(c[0]), "+f"(c[1]), "+f"(c[2]), "+f"(c[3])
        : "r"(a[0]), "r"(a[1]), "r"(a[2]), "r"(a[3]), "r"(b[0]), "r"(b[1]));
}

// ======================= fp32 -> fp16 activation convert =====================
__global__ __launch_bounds__(256) void convert3(
    const float* __restrict__ i0, const float* __restrict__ i1,
    const float* __restrict__ i2, __half* __restrict__ outbase)
{
    const int z = blockIdx.y;
    const float* in = (z == 0) ? i0 : (z == 1) ? i1 : i2;
    __half* out = outbase + (size_t)z * 8192u * 1024u;

    const size_t idx = (size_t)blockIdx.x * 256 + threadIdx.x;
    const float4* ip = (const float4*)in + idx * 2;
    float4 a = ip[0], b = ip[1];
    uint4 o;
    o.x = h2u(__float22half2_rn(make_float2(a.x, a.y)));
    o.y = h2u(__float22half2_rn(make_float2(a.z, a.w)));
    o.z = h2u(__float22half2_rn(make_float2(b.x, b.y)));
    o.w = h2u(__float22half2_rn(make_float2(b.z, b.w)));
    *((uint4*)out + idx) = o;
}

// ======================= batched weight transpose -> fp16 ====================
__global__ __launch_bounds__(256) void transpose_kernel(
    const float* __restrict__ w0, const float* __restrict__ w1,
    const float* __restrict__ w2, const float* __restrict__ w3,
    __half* __restrict__ outbase)
{
    const int z = blockIdx.z;
    const float* in = (z == 0) ? w0 : (z == 1) ? w1 : (z == 2) ? w2 : w3;
    __half* out = outbase + (size_t)z * 1024u * 1024u;

    __shared__ float t[32][33];
    const int bx = blockIdx.x * 32, by = blockIdx.y * 32;
    const int tx = threadIdx.x & 31, ty4 = (threadIdx.x >> 5) * 4;
#pragma unroll
    for (int i = 0; i < 4; i++)
        t[ty4 + i][tx] = in[(size_t)(by + ty4 + i) * 1024 + bx + tx];
    __syncthreads();
#pragma unroll
    for (int i = 0; i < 4; i++)
        out[(size_t)(bx + ty4 + i) * 1024 + by + tx] = __float2half_rn(t[tx][ty4 + i]);
}

// ======================= fp16 GEMM: C = A @ Bt^T =============================
#define PADU 20
#define STG_U32 (256 * PADU)
#define GEMM_SMEM (3 * STG_U32 * 4)         // 61440 bytes

__global__ __launch_bounds__(256, 2) void gemm16(
    const __half* __restrict__ Abase, const __half* __restrict__ Wt,
    __half* __restrict__ Ch0, __half* __restrict__ Ch1, __half* __restrict__ Ch2,
    float* __restrict__ Cf, int headed)
{
    extern __shared__ uint32_t shu[];

    const int z = blockIdx.z;
    const __half* A = Abase + (size_t)z * 8192u * 1024u;
    const __half* Bt = Wt + (size_t)z * 1024u * 1024u;
    __half* Ch = (z == 0) ? Ch0 : (z == 1) ? Ch1 : Ch2;

    const int tid = threadIdx.x;
    const int lane = tid & 31;
    const int w = tid >> 5;
    const int g = lane >> 2, t = lane & 3;
    const int wm = (w >> 2) * 64;
    const int wn = (w & 3) * 32;
    const int m0 = blockIdx.y * 128;
    const int n0 = blockIdx.x * 128;

    int row_[2], q_[2];
#pragma unroll
    for (int i = 0; i < 2; i++) {
        int s = tid * 2 + i;
        row_[i] = s >> 2; q_[i] = s & 3;
    }
    const uint32_t sb = smem_u32(shu);

    float acc[4][4][4];
#pragma unroll
    for (int mt = 0; mt < 4; mt++)
#pragma unroll
        for (int nt = 0; nt < 4; nt++)
#pragma unroll
            for (int r = 0; r < 4; r++) acc[mt][nt][r] = 0.f;

#pragma unroll
    for (int st = 0; st < 2; st++) {
        const uint32_t base = sb + st * STG_U32 * 4;
        const int k0 = st * 32;
#pragma unroll
        for (int i = 0; i < 2; i++) {
            cp16(base + (row_[i] * PADU + q_[i] * 4) * 4,
                 A + (size_t)(m0 + row_[i]) * 1024 + k0 + q_[i] * 8);
            cp16(base + ((128 + row_[i]) * PADU + q_[i] * 4) * 4,
                 Bt + (size_t)(n0 + row_[i]) * 1024 + k0 + q_[i] * 8);
        }
        asm volatile("cp.async.commit_group;" ::: "memory");
    }

    for (int it = 0; it < 32; it++) {
        asm volatile("cp.async.wait_group 1;" ::: "memory");
        __syncthreads();

        if (it + 2 < 32) {
            const int st = (it + 2) % 3;
            const uint32_t base = sb + st * STG_U32 * 4;
            const int k0 = (it + 2) * 32;
#pragma unroll
            for (int i = 0; i < 2; i++) {
                cp16(base + (row_[i] * PADU + q_[i] * 4) * 4,
                     A + (size_t)(m0 + row_[i]) * 1024 + k0 + q_[i] * 8);
                cp16(base + ((128 + row_[i]) * PADU + q_[i] * 4) * 4,
                     Bt + (size_t)(n0 + row_[i]) * 1024 + k0 + q_[i] * 8);
            }
            asm volatile("cp.async.commit_group;" ::: "memory");
        }

        const uint32_t* As = shu + (it % 3) * STG_U32;
        const uint32_t* Bs = As + 128 * PADU;
#pragma unroll
        for (int ksu = 0; ksu < 16; ksu += 8) {
            uint32_t af[4][4], bf[4][2];
#pragma unroll
            for (int mt = 0; mt < 4; mt++) {
                int rb = wm + mt * 16 + g;
                af[mt][0] = As[rb * PADU + ksu + t];
                af[mt][1] = As[(rb + 8) * PADU + ksu + t];
                af[mt][2] = As[rb * PADU + ksu + t + 4];
                af[mt][3] = As[(rb + 8) * PADU + ksu + t + 4];
            }
#pragma unroll
            for (int nt = 0; nt < 4; nt++) {
                int cb = wn + nt * 8 + g;
                bf[nt][0] = Bs[cb * PADU + ksu + t];
                bf[nt][1] = Bs[cb * PADU + ksu + t + 4];
            }
#pragma unroll
            for (int mt = 0; mt < 4; mt++)
#pragma unroll
                for (int nt = 0; nt < 4; nt++)
                    mma_f16(acc[mt][nt], af[mt], bf[nt]);
        }
    }

#pragma unroll
    for (int mt = 0; mt < 4; mt++) {
        int r0 = m0 + wm + mt * 16 + g;
        int r1 = r0 + 8;
#pragma unroll
        for (int nt = 0; nt < 4; nt++) {
            int c = n0 + wn + nt * 8 + 2 * t;
            if (!headed) {
                *(float2*)(Cf + (size_t)r0 * 1024 + c) =
                    make_float2(acc[mt][nt][0], acc[mt][nt][1]);
                *(float2*)(Cf + (size_t)r1 * 1024 + c) =
                    make_float2(acc[mt][nt][2], acc[mt][nt][3]);
            } else {
                int b = r0 >> 10;
                int h = c >> 6, d = c & 63;
                __half2 v0 = __float22half2_rn(make_float2(acc[mt][nt][0], acc[mt][nt][1]));
                __half2 v1 = __float22half2_rn(make_float2(acc[mt][nt][2], acc[mt][nt][3]));
                *(__half2*)(Ch + (((size_t)b * Hc + h) * Sc + (r0 & 1023)) * DKc + d) = v0;
                *(__half2*)(Ch + (((size_t)b * Hc + h) * Sc + (r1 & 1023)) * DKc + d) = v1;
            }
        }
    }
}

// ======================= scores: exp(QK^T/8) -> fp16 P~ + row partial sums ===
// Lower-tri tiles only; P~ fp16 to P16, row-tile sums to rsp. No attn writes.
#define SPADU 36
#define SCORES_SMEM (2 * 128 * SPADU * 4)   // 36864 bytes

__global__ __launch_bounds__(256) void scores_mma(
    const __half* __restrict__ Q, const __half* __restrict__ K,
    __half* __restrict__ P16, float* __restrict__ rsp)
{
    const int kt = blockIdx.x;
    const int qt = blockIdx.y;
    const int bh = blockIdx.z;
    if (kt > qt) return;

    extern __shared__ uint32_t shs[];
    uint32_t* Qs = shs;
    uint32_t* Ks = shs + 128 * SPADU;
    __shared__ float sp[128][4];

    const int tid = threadIdx.x;
    const int lane = tid & 31;
    const int w = tid >> 5;
    const int g = lane >> 2, t = lane & 3;
    const int wm = (w >> 2) * 64;
    const int wn = (w & 3) * 32;

    const __half* Qb = Q + ((size_t)bh * Sc + qt * 128) * DKc;
    const __half* Kb = K + ((size_t)bh * Sc + kt * 128) * DKc;

#pragma unroll
    for (int i = 0; i < 4; i++) {
        int s = i * 256 + tid;
        int row = s >> 3, q = s & 7;
        *(uint4*)&Qs[row * SPADU + q * 4] =
            *(const uint4*)(Qb + (size_t)row * DKc + q * 8);
        *(uint4*)&Ks[row * SPADU + q * 4] =
            *(const uint4*)(Kb + (size_t)row * DKc + q * 8);
    }
    __syncthreads();

    float acc[4][4][4];
#pragma unroll
    for (int mt = 0; mt < 4; mt++)
#pragma unroll
        for (int nt = 0; nt < 4; nt++)
#pragma unroll
            for (int r = 0; r < 4; r++) acc[mt][nt][r] = 0.f;

#pragma unroll
    for (int ksu = 0; ksu < 32; ksu += 8) {
        uint32_t af[4][4], bf[4][2];
#pragma unroll
        for (int mt = 0; mt < 4; mt++) {
            int rb = wm + mt * 16 + g;
            af[mt][0] = Qs[rb * SPADU + ksu + t];
            af[mt][1] = Qs[(rb + 8) * SPADU + ksu + t];
            af[mt][2] = Qs[rb * SPADU + ksu + t + 4];
            af[mt][3] = Qs[(rb + 8) * SPADU + ksu + t + 4];
        }
#pragma unroll
        for (int nt = 0; nt < 4; nt++) {
            int cb = wn + nt * 8 + g;
            bf[nt][0] = Ks[cb * SPADU + ksu + t];
            bf[nt][1] = Ks[cb * SPADU + ksu + t + 4];
        }
#pragma unroll
        for (int mt = 0; mt < 4; mt++)
#pragma unroll
            for (int nt = 0; nt < 4; nt++)
                mma_f16(acc[mt][nt], af[mt], bf[nt]);
    }

    const bool diag = (kt == qt);
#pragma unroll
    for (int mt = 0; mt < 4; mt++) {
        int lr0 = wm + mt * 16 + g;
        int lr1 = lr0 + 8;
        int r0 = qt * 128 + lr0;
        int r1 = r0 + 8;
        float rs0 = 0.f, rs1 = 0.f;
#pragma unroll
        for (int nt = 0; nt < 4; nt++) {
            int c = kt * 128 + wn + nt * 8 + 2 * t;
            float e00 = __expf(acc[mt][nt][0] * 0.125f);
            float e01 = __expf(acc[mt][nt][1] * 0.125f);
            float e10 = __expf(acc[mt][nt][2] * 0.125f);
            float e11 = __expf(acc[mt][nt][3] * 0.125f);
            if (diag) {
                if (c > r0) e00 = 0.f;
                if (c + 1 > r0) e01 = 0.f;
                if (c > r1) e10 = 0.f;
                if (c + 1 > r1) e11 = 0.f;
            }
            rs0 += e00 + e01;
            rs1 += e10 + e11;
            *(__half2*)(P16 + ((size_t)bh * Sc + r0) * Sc + c) =
                __float22half2_rn(make_float2(e00, e01));
            *(__half2*)(P16 + ((size_t)bh * Sc + r1) * Sc + c) =
                __float22half2_rn(make_float2(e10, e11));
        }
        rs0 += __shfl_xor_sync(0xffffffffu, rs0, 1);
        rs0 += __shfl_xor_sync(0xffffffffu, rs0, 2);
        rs1 += __shfl_xor_sync(0xffffffffu, rs1, 1);
        rs1 += __shfl_xor_sync(0xffffffffu, rs1, 2);
        if (t == 0) {
            sp[lr0][w & 3] = rs0;
            sp[lr1][w & 3] = rs1;
        }
    }
    __syncthreads();
    if (tid < 128) {
        float s = sp[tid][0] + sp[tid][1] + sp[tid][2] + sp[tid][3];
        rsp[((size_t)bh * 8 + kt) * 1024 + qt * 128 + tid] = s;
    }
}

// ======================= context: raw fp16 P~, normalize at epilogue =========
#define CPADU 36
#define CTX_SMEM ((128 * CPADU + 64 * CPADU) * 4)   // 27648 bytes

__global__ __launch_bounds__(256) void context_mma(
    const __half* __restrict__ P16, const __half* __restrict__ V,
    __half* __restrict__ ctx, const float* __restrict__ rsp)
{
    const int qt = (int)gridDim.x - 1 - (int)blockIdx.x;  // longest-job-first
    const int bh = blockIdx.y;

    extern __shared__ uint32_t shc[];
    uint32_t* Ps = shc;                 // [128 q][CPADU]  (fp16 pairs)
    uint32_t* Vs = shc + 128 * CPADU;   // [64 d][CPADU]
    __shared__ float sinv[128];

    const int tid = threadIdx.x;
    const int lane = tid & 31;
    const int w = tid >> 5;
    const int g = lane >> 2, t = lane & 3;
    const int wm = (w >> 1) * 32;
    const int wn = (w & 1) * 32;

    const int nst = 2 * (qt + 1);

    if (tid < 128) {
        float s = 0.f;
        for (int kt = 0; kt <= qt; kt++)
            s += rsp[((size_t)bh * 8 + kt) * 1024 + qt * 128 + tid];
        sinv[tid] = 1.f / s;
    }

    float acc[2][4][4];
#pragma unroll
    for (int mt = 0; mt < 2; mt++)
#pragma unroll
        for (int nt = 0; nt < 4; nt++)
#pragma unroll
            for (int r = 0; r < 4; r++) acc[mt][nt][r] = 0.f;

    const __half* Pb = P16 + ((size_t)bh * Sc + qt * 128) * Sc;
    const __half* Vb = V + (size_t)bh * Sc * DKc;

    uint4 pph[4];
    uint2 pv0[2], pv1[2];

    // prefetch stage 0: P fp16 tile 128x64 = 1024 uint4, 4/thread
#pragma unroll
    for (int i = 0; i < 4; i++) {
        int s = i * 256 + tid;
        int row = s >> 3, q = s & 7;
        pph[i] = *(const uint4*)(Pb + (size_t)row * Sc + q * 8);
    }
#pragma unroll
    for (int j = 0; j < 2; j++) {
        int u = tid * 2 + j;
        int ku = u >> 4, dq = u & 15;
        pv0[j] = *(const uint2*)(Vb + (size_t)(2 * ku) * DKc + dq * 4);
        pv1[j] = *(const uint2*)(Vb + (size_t)(2 * ku + 1) * DKc + dq * 4);
    }
#pragma unroll
    for (int i = 0; i < 4; i++) {
        int s = i * 256 + tid;
        int row = s >> 3, q = s & 7;
        *(uint4*)&Ps[row * CPADU + q * 4] = pph[i];
    }
#pragma unroll
    for (int j = 0; j < 2; j++) {
        int u = tid * 2 + j;
        int ku = u >> 4, dq = u & 15;
        __half2 a0 = *reinterpret_cast<__half2*>(&pv0[j].x);
        __half2 a1 = *reinterpret_cast<__half2*>(&pv0[j].y);
        __half2 b0 = *reinterpret_cast<__half2*>(&pv1[j].x);
        __half2 b1 = *reinterpret_cast<__half2*>(&pv1[j].y);
        Vs[(dq * 4 + 0) * CPADU + ku] = h2u(__halves2half2(__low2half(a0), __low2half(b0)));
        Vs[(dq * 4 + 1) * CPADU + ku] = h2u(__halves2half2(__high2half(a0), __high2half(b0)));
        Vs[(dq * 4 + 2) * CPADU + ku] = h2u(__halves2half2(__low2half(a1), __low2half(b1)));
        Vs[(dq * 4 + 3) * CPADU + ku] = h2u(__halves2half2(__high2half(a1), __high2half(b1)));
    }
    __syncthreads();

    for (int st = 0; st < nst; st++) {
        if (st + 1 < nst) {
            const int kk = (st + 1) * 64;
#pragma unroll
            for (int i = 0; i < 4; i++) {
                int s = i * 256 + tid;
                int row = s >> 3, q = s & 7;
                pph[i] = *(const uint4*)(Pb + (size_t)row * Sc + kk + q * 8);
            }
#pragma unroll
            for (int j = 0; j < 2; j++) {
                int u = tid * 2 + j;
                int ku = u >> 4, dq = u & 15;
                pv0[j] = *(const uint2*)(Vb + (size_t)(kk + 2 * ku) * DKc + dq * 4);
                pv1[j] = *(const uint2*)(Vb + (size_t)(kk + 2 * ku + 1) * DKc + dq * 4);
            }
        }

#pragma unroll
        for (int ksu = 0; ksu < 32; ksu += 8) {
            uint32_t af[2][4], bf[4][2];
#pragma unroll
            for (int mt = 0; mt < 2; mt++) {
                int rb = wm + mt * 16 + g;
                af[mt][0] = Ps[rb * CPADU + ksu + t];
                af[mt][1] = Ps[(rb + 8) * CPADU + ksu + t];
                af[mt][2] = Ps[rb * CPADU + ksu + t + 4];
                af[mt][3] = Ps[(rb + 8) * CPADU + ksu + t + 4];
            }
#pragma unroll
            for (int nt = 0; nt < 4; nt++) {
                int cb = wn + nt * 8 + g;
                bf[nt][0] = Vs[cb * CPADU + ksu + t];
                bf[nt][1] = Vs[cb * CPADU + ksu + t + 4];
            }
#pragma unroll
            for (int mt = 0; mt < 2; mt++)
#pragma unroll
                for (int nt = 0; nt < 4; nt++)
                    mma_f16(acc[mt][nt], af[mt], bf[nt]);
        }

        if (st + 1 < nst) {
            __syncthreads();
#pragma unroll
            for (int i = 0; i < 4; i++) {
                int s = i * 256 + tid;
                int row = s >> 3, q = s & 7;
                *(uint4*)&Ps[row * CPADU + q * 4] = pph[i];
            }
#pragma unroll
            for (int j = 0; j < 2; j++) {
                int u = tid * 2 + j;
                int ku = u >> 4, dq = u & 15;
                __half2 a0 = *reinterpret_cast<__half2*>(&pv0[j].x);
                __half2 a1 = *reinterpret_cast<__half2*>(&pv0[j].y);
                __half2 b0 = *reinterpret_cast<__half2*>(&pv1[j].x);
                __half2 b1 = *reinterpret_cast<__half2*>(&pv1[j].y);
                Vs[(dq * 4 + 0) * CPADU + ku] = h2u(__halves2half2(__low2half(a0), __low2half(b0)));
                Vs[(dq * 4 + 1) * CPADU + ku] = h2u(__halves2half2(__high2half(a0), __high2half(b0)));
                Vs[(dq * 4 + 2) * CPADU + ku] = h2u(__halves2half2(__low2half(a1), __low2half(b1)));
                Vs[(dq * 4 + 3) * CPADU + ku] = h2u(__halves2half2(__high2half(a1), __high2half(b1)));
            }
            __syncthreads();
        }
    }

    const int b = bh >> 4;
    const int h = bh & 15;
#pragma unroll
    for (int mt = 0; mt < 2; mt++) {
        int lq0 = wm + mt * 16 + g;
        int lq1 = lq0 + 8;
        int q0 = qt * 128 + lq0;
        int q1 = q0 + 8;
        float i0 = sinv[lq0], i1 = sinv[lq1];
#pragma unroll
        for (int nt = 0; nt < 4; nt++) {
            int c = wn + nt * 8 + 2 * t;
            __half2 v0 = __float22half2_rn(make_float2(acc[mt][nt][0] * i0,
                                                       acc[mt][nt][1] * i0));
            __half2 v1 = __float22half2_rn(make_float2(acc[mt][nt][2] * i1,
                                                       acc[mt][nt][3] * i1));
            *(__half2*)(ctx + ((size_t)b * Sc + q0) * Dc + h * 64 + c) = v0;
            *(__half2*)(ctx + ((size_t)b * Sc + q1) * Dc + h * 64 + c) = v1;
        }
    }
}

// ======================= attn finalize: full fp32 attn output ================
// Warp-per-row: j < end -> P~ * inv (P16 has masked zeros in diag tile);
// j >= end -> 0. end = (qt+1)*128.
__global__ __launch_bounds__(256) void attn_final(
    const __half* __restrict__ P16, const float* __restrict__ rsp,
    float* __restrict__ attn)
{
    const int wid = threadIdx.x >> 5, lane = threadIdx.x & 31;
    const int q = blockIdx.x * 8 + wid;
    const int bh = blockIdx.y;
    const int qt = q >> 7;
    const int end = (qt + 1) << 7;

    float s = 0.f;
    for (int kt = 0; kt <= qt; kt++)
        s += rsp[((size_t)bh * 8 + kt) * 1024 + q];
    const float inv = 1.f / s;

    const __half* pr = P16 + ((size_t)bh * Sc + q) * Sc;
    float* ar = attn + ((size_t)bh * Sc + q) * Sc;

    for (int j4 = lane * 4; j4 < end; j4 += 128) {
        uint2 ph = *(const uint2*)(pr + j4);
        float2 f0 = __half22float2(*reinterpret_cast<__half2*>(&ph.x));
        float2 f1 = __half22float2(*reinterpret_cast<__half2*>(&ph.y));
        *(float4*)(ar + j4) = make_float4(f0.x * inv, f0.y * inv,
                                          f1.x * inv, f1.y * inv);
    }
    const float4 z4 = make_float4(0.f, 0.f, 0.f, 0.f);
    for (int j4 = end + lane * 4; j4 < Sc; j4 += 128)
        *(float4*)(ar + j4) = z4;
}

// ---------------- warp-per-row residual + LayerNorm -------------------------
__global__ __launch_bounds__(256) void addln_warp(
    const float* __restrict__ fc, const float* __restrict__ resid,
    float* __restrict__ out)
{
    const int wid = threadIdx.x >> 5, lane = threadIdx.x & 31;
    const int m = blockIdx.x * 8 + wid;

    __shared__ float xr[8][1024];
    const float* fp = fc + (size_t)m * Dc;
    const float* rp = resid + (size_t)m * Dc;

    float s = 0.f;
#pragma unroll
    for (int j4 = lane * 4; j4 < Dc; j4 += 128) {
        float4 a = *(const float4*)(fp + j4);
        float4 b = *(const float4*)(rp + j4);
        float4 x = make_float4(a.x + b.x, a.y + b.y, a.z + b.z, a.w + b.w);
        *(float4*)&xr[wid][j4] = x;
        s += x.x + x.y + x.z + x.w;
    }
#pragma unroll
    for (int o = 16; o; o >>= 1) s += __shfl_xor_sync(0xffffffffu, s, o);
    const float mu = s * (1.f / 1024.f);

    float ss = 0.f;
#pragma unroll
    for (int j4 = lane * 4; j4 < Dc; j4 += 128) {
        float4 x = *(const float4*)&xr[wid][j4];
        float dx = x.x - mu, dy = x.y - mu, dz = x.z - mu, dw = x.w - mu;
        ss += dx * dx + dy * dy + dz * dz + dw * dw;
    }
#pragma unroll
    for (int o = 16; o; o >>= 1) ss += __shfl_xor_sync(0xffffffffu, ss, o);
    const float inv = rsqrtf(ss * (1.f / 1024.f) + 1e-5f);

    float* op = out + (size_t)m * Dc;
#pragma unroll
    for (int j4 = lane * 4; j4 < Dc; j4 += 128) {
        float4 x = *(const float4*)&xr[wid][j4];
        *(float4*)(op + j4) = make_float4((x.x - mu) * inv, (x.y - mu) * inv,
                                          (x.z - mu) * inv, (x.w - mu) * inv);
    }
}

// ---------------- launch -----------------------------------------------------
extern "C" void kernel_launch(void* const* d_in, const int* in_sizes, int n_in,
                              void* d_out, int out_size)
{
    const float* inQ = (const float*)d_in[0];
    const float* inK = (const float*)d_in[1];
    const float* inV = (const float*)d_in[2];
    // d_in[3] = causal mask (fixed triu) — implemented analytically
    const float* Wq = (const float*)d_in[4];
    const float* Wk = (const float*)d_in[5];
    const float* Wv = (const float*)d_in[6];
    const float* Wfc = (const float*)d_in[7];

    float* out = (float*)d_out;                       // [B,S,D]
    float* attn = out + (size_t)Bc * Sc * Dc;         // [B,H,S,S]

    __half *pA16, *pQ16, *pK16, *pV16, *pctx16, *pWt16, *pP16;
    float *pfc, *prsp;
    cudaGetSymbolAddress((void**)&pA16, g_A16);
    cudaGetSymbolAddress((void**)&pQ16, g_Q16);
    cudaGetSymbolAddress((void**)&pK16, g_K16);
    cudaGetSymbolAddress((void**)&pV16, g_V16);
    cudaGetSymbolAddress((void**)&pctx16, g_ctx16);
    cudaGetSymbolAddress((void**)&pfc, g_fc);
    cudaGetSymbolAddress((void**)&pWt16, g_Wt16);
    cudaGetSymbolAddress((void**)&pP16, g_P16);
    cudaGetSymbolAddress((void**)&prsp, g_rsp);

    cudaFuncSetAttribute(gemm16,
                         cudaFuncAttributeMaxDynamicSharedMemorySize, GEMM_SMEM);
    cudaFuncSetAttribute(scores_mma,
                         cudaFuncAttributeMaxDynamicSharedMemorySize, SCORES_SMEM);
    cudaFuncSetAttribute(context_mma,
                         cudaFuncAttributeMaxDynamicSharedMemorySize, CTX_SMEM);

    const size_t WSZ = 1024u * 1024u;
    convert3<<<dim3(4096, 3), 256>>>(inQ, inK, inV, pA16);
    transpose_kernel<<<dim3(32, 32, 4), 256>>>(Wq, Wk, Wv, Wfc, pWt16);

    // batched Q,K,V projections, fp16 headed outputs
    gemm16<<<dim3(8, 64, 3), 256, GEMM_SMEM>>>(
        pA16, pWt16, pQ16, pK16, pV16, nullptr, 1);

    scores_mma<<<dim3(8, 8, Bc * Hc), 256, SCORES_SMEM>>>(
        pQ16, pK16, pP16, prsp);
    context_mma<<<dim3(8, Bc * Hc), 256, CTX_SMEM>>>(
        pP16, pV16, pctx16, prsp);
    attn_final<<<dim3(Sc / 8, Bc * Hc), 256>>>(pP16, prsp, attn);

    // FC GEMM: A = ctx fp16 (flat), weight slice 3, fp32 flat output
    gemm16<<<dim3(8, 64, 1), 256, GEMM_SMEM>>>(
        pctx16, pWt16 + 3 * WSZ, nullptr, nullptr, nullptr, pfc, 0);

    addln_warp<<<Bc * Sc / 8, 256>>>(pfc, inQ, out);
}

// round 17
// speedup vs baseline: 1.5138x; 1.5138x over previous
#include <cuda_runtime.h>
#include <cuda_fp16.h>
#include <cstdint>

#define Bc 8
#define Sc 1024
#define Dc 1024
#define Hc 16
#define DKc 64

// ---------------- scratch (static device globals; no allocation) -------------
__device__ __half g_A16[3u * 8192u * 1024u];        // fp16 inQ/inK/inV
__device__ __half g_Q16[(size_t)Bc * Hc * Sc * DKc];  // [b,h,s,dk] fp16
__device__ __half g_K16[(size_t)Bc * Hc * Sc * DKc];
__device__ __half g_V16[(size_t)Bc * Hc * Sc * DKc];
__device__ __half g_ctx16[(size_t)Bc * Sc * Dc];    // [m][1024] fp16
__device__ float  g_fc[(size_t)Bc * Sc * Dc];
__device__ __half g_Wt16[4u * 1024u * 1024u];       // transposed fp16 [n][k]
__device__ float  g_rsp[128u * 8u * 1024u];         // row-sum partials [bh][kt][q]

// ======================= helpers =============================================
__device__ __forceinline__ uint32_t smem_u32(const void* p) {
    uint32_t a;
    asm("{ .reg .u64 t; cvta.to.shared.u64 t, %1; cvt.u32.u64 %0, t; }"
        : "=r"(a) : "l"(p));
    return a;
}

__device__ __forceinline__ void cp16(uint32_t s, const void* g) {
    asm volatile("cp.async.cg.shared.global [%0], [%1], 16;"
                 :: "r"(s), "l"(g) : "memory");
}

__device__ __forceinline__ uint32_t h2u(__half2 h) {
    return *reinterpret_cast<uint32_t*>(&h);
}

// mma.sync m16n8k16 fp16->fp32 (base sm_80+ ISA)
__device__ __forceinline__ void mma_f16(float* c, const uint32_t* a,
                                        const uint32_t* b) {
    asm volatile(
        "mma.sync.aligned.m16n8k16.row.col.f32.f16.f16.f32 "
        "{%0,%1,%2,%3}, {%4,%5,%6,%7}, {%8,%9}, {%0,%1,%2,%3};"
        : "+f"(c[0]), "+f"(c[1]), "+f"(c[2]), "+f"(c[3])
        : "r"(a[0]), "r"(a[1]), "r"(a[2]), "r"(a[3]), "r"(b[0]), "r"(b[1]));
}

// ======================= fp32 -> fp16 activation convert =====================
__global__ __launch_bounds__(256) void convert3(
    const float* __restrict__ i0, const float* __restrict__ i1,
    const float* __restrict__ i2, __half* __restrict__ outbase)
{
    const int z = blockIdx.y;
    const float* in = (z == 0) ? i0 : (z == 1) ? i1 : i2;
    __half* out = outbase + (size_t)z * 8192u * 1024u;

    const size_t idx = (size_t)blockIdx.x * 256 + threadIdx.x;
    const float4* ip = (const float4*)in + idx * 2;
    float4 a = ip[0], b = ip[1];
    uint4 o;
    o.x = h2u(__float22half2_rn(make_float2(a.x, a.y)));
    o.y = h2u(__float22half2_rn(make_float2(a.z, a.w)));
    o.z = h2u(__float22half2_rn(make_float2(b.x, b.y)));
    o.w = h2u(__float22half2_rn(make_float2(b.z, b.w)));
    *((uint4*)out + idx) = o;
}

// ======================= batched weight transpose -> fp16 ====================
__global__ __launch_bounds__(256) void transpose_kernel(
    const float* __restrict__ w0, const float* __restrict__ w1,
    const float* __restrict__ w2, const float* __restrict__ w3,
    __half* __restrict__ outbase)
{
    const int z = blockIdx.z;
    const float* in = (z == 0) ? w0 : (z == 1) ? w1 : (z == 2) ? w2 : w3;
    __half* out = outbase + (size_t)z * 1024u * 1024u;

    __shared__ float t[32][33];
    const int bx = blockIdx.x * 32, by = blockIdx.y * 32;
    const int tx = threadIdx.x & 31, ty4 = (threadIdx.x >> 5) * 4;
#pragma unroll
    for (int i = 0; i < 4; i++)
        t[ty4 + i][tx] = in[(size_t)(by + ty4 + i) * 1024 + bx + tx];
    __syncthreads();
#pragma unroll
    for (int i = 0; i < 4; i++)
        out[(size_t)(bx + ty4 + i) * 1024 + by + tx] = __float2half_rn(t[tx][ty4 + i]);
}

// ======================= fp16 GEMM: C = A @ Bt^T =============================
#define PADU 20
#define STG_U32 (256 * PADU)
#define GEMM_SMEM (3 * STG_U32 * 4)         // 61440 bytes

__global__ __launch_bounds__(256, 2) void gemm16(
    const __half* __restrict__ Abase, const __half* __restrict__ Wt,
    __half* __restrict__ Ch0, __half* __restrict__ Ch1, __half* __restrict__ Ch2,
    float* __restrict__ Cf, int headed)
{
    extern __shared__ uint32_t shu[];

    const int z = blockIdx.z;
    const __half* A = Abase + (size_t)z * 8192u * 1024u;
    const __half* Bt = Wt + (size_t)z * 1024u * 1024u;
    __half* Ch = (z == 0) ? Ch0 : (z == 1) ? Ch1 : Ch2;

    const int tid = threadIdx.x;
    const int lane = tid & 31;
    const int w = tid >> 5;
    const int g = lane >> 2, t = lane & 3;
    const int wm = (w >> 2) * 64;
    const int wn = (w & 3) * 32;
    const int m0 = blockIdx.y * 128;
    const int n0 = blockIdx.x * 128;

    int row_[2], q_[2];
#pragma unroll
    for (int i = 0; i < 2; i++) {
        int s = tid * 2 + i;
        row_[i] = s >> 2; q_[i] = s & 3;
    }
    const uint32_t sb = smem_u32(shu);

    float acc[4][4][4];
#pragma unroll
    for (int mt = 0; mt < 4; mt++)
#pragma unroll
        for (int nt = 0; nt < 4; nt++)
#pragma unroll
            for (int r = 0; r < 4; r++) acc[mt][nt][r] = 0.f;

#pragma unroll
    for (int st = 0; st < 2; st++) {
        const uint32_t base = sb + st * STG_U32 * 4;
        const int k0 = st * 32;
#pragma unroll
        for (int i = 0; i < 2; i++) {
            cp16(base + (row_[i] * PADU + q_[i] * 4) * 4,
                 A + (size_t)(m0 + row_[i]) * 1024 + k0 + q_[i] * 8);
            cp16(base + ((128 + row_[i]) * PADU + q_[i] * 4) * 4,
                 Bt + (size_t)(n0 + row_[i]) * 1024 + k0 + q_[i] * 8);
        }
        asm volatile("cp.async.commit_group;" ::: "memory");
    }

    for (int it = 0; it < 32; it++) {
        asm volatile("cp.async.wait_group 1;" ::: "memory");
        __syncthreads();

        if (it + 2 < 32) {
            const int st = (it + 2) % 3;
            const uint32_t base = sb + st * STG_U32 * 4;
            const int k0 = (it + 2) * 32;
#pragma unroll
            for (int i = 0; i < 2; i++) {
                cp16(base + (row_[i] * PADU + q_[i] * 4) * 4,
                     A + (size_t)(m0 + row_[i]) * 1024 + k0 + q_[i] * 8);
                cp16(base + ((128 + row_[i]) * PADU + q_[i] * 4) * 4,
                     Bt + (size_t)(n0 + row_[i]) * 1024 + k0 + q_[i] * 8);
            }
            asm volatile("cp.async.commit_group;" ::: "memory");
        }

        const uint32_t* As = shu + (it % 3) * STG_U32;
        const uint32_t* Bs = As + 128 * PADU;
#pragma unroll
        for (int ksu = 0; ksu < 16; ksu += 8) {
            uint32_t af[4][4], bf[4][2];
#pragma unroll
            for (int mt = 0; mt < 4; mt++) {
                int rb = wm + mt * 16 + g;
                af[mt][0] = As[rb * PADU + ksu + t];
                af[mt][1] = As[(rb + 8) * PADU + ksu + t];
                af[mt][2] = As[rb * PADU + ksu + t + 4];
                af[mt][3] = As[(rb + 8) * PADU + ksu + t + 4];
            }
#pragma unroll
            for (int nt = 0; nt < 4; nt++) {
                int cb = wn + nt * 8 + g;
                bf[nt][0] = Bs[cb * PADU + ksu + t];
                bf[nt][1] = Bs[cb * PADU + ksu + t + 4];
            }
#pragma unroll
            for (int mt = 0; mt < 4; mt++)
#pragma unroll
                for (int nt = 0; nt < 4; nt++)
                    mma_f16(acc[mt][nt], af[mt], bf[nt]);
        }
    }

#pragma unroll
    for (int mt = 0; mt < 4; mt++) {
        int r0 = m0 + wm + mt * 16 + g;
        int r1 = r0 + 8;
#pragma unroll
        for (int nt = 0; nt < 4; nt++) {
            int c = n0 + wn + nt * 8 + 2 * t;
            if (!headed) {
                *(float2*)(Cf + (size_t)r0 * 1024 + c) =
                    make_float2(acc[mt][nt][0], acc[mt][nt][1]);
                *(float2*)(Cf + (size_t)r1 * 1024 + c) =
                    make_float2(acc[mt][nt][2], acc[mt][nt][3]);
            } else {
                int b = r0 >> 10;
                int h = c >> 6, d = c & 63;
                __half2 v0 = __float22half2_rn(make_float2(acc[mt][nt][0], acc[mt][nt][1]));
                __half2 v1 = __float22half2_rn(make_float2(acc[mt][nt][2], acc[mt][nt][3]));
                *(__half2*)(Ch + (((size_t)b * Hc + h) * Sc + (r0 & 1023)) * DKc + d) = v0;
                *(__half2*)(Ch + (((size_t)b * Hc + h) * Sc + (r1 & 1023)) * DKc + d) = v1;
            }
        }
    }
}

// ======================= scores: exp(QK^T/8) + row partial sums ==============
// Stores UNNORMALIZED exp scores (masked to 0 above diagonal); writes per-tile
// row sums to g_rsp[bh][kt][q]. Upper tiles (kt>qt): zero-fill.
#define SPADU 36
#define SCORES_SMEM (2 * 128 * SPADU * 4)   // 36864 bytes

__global__ __launch_bounds__(256, 2) void scores_mma(
    const __half* __restrict__ Q, const __half* __restrict__ K,
    float* __restrict__ attn, float* __restrict__ rsp)
{
    const int kt = blockIdx.x;
    const int qt = blockIdx.y;
    const int bh = blockIdx.z;

    if (kt > qt) {
        const int tid = threadIdx.x;
        float4 z4 = make_float4(0.f, 0.f, 0.f, 0.f);
#pragma unroll
        for (int i = 0; i < 16; i++) {
            int f4 = i * 256 + tid;
            int row = f4 >> 5, col = (f4 & 31) << 2;
            *(float4*)(attn + ((size_t)bh * Sc + qt * 128 + row) * Sc
                       + kt * 128 + col) = z4;
        }
        return;
    }

    extern __shared__ uint32_t shs[];
    uint32_t* Qs = shs;
    uint32_t* Ks = shs + 128 * SPADU;
    __shared__ float sp[128][4];

    const int tid = threadIdx.x;
    const int lane = tid & 31;
    const int w = tid >> 5;
    const int g = lane >> 2, t = lane & 3;
    const int wm = (w >> 2) * 64;
    const int wn = (w & 3) * 32;

    const __half* Qb = Q + ((size_t)bh * Sc + qt * 128) * DKc;
    const __half* Kb = K + ((size_t)bh * Sc + kt * 128) * DKc;

#pragma unroll
    for (int i = 0; i < 4; i++) {
        int s = i * 256 + tid;
        int row = s >> 3, q = s & 7;
        *(uint4*)&Qs[row * SPADU + q * 4] =
            *(const uint4*)(Qb + (size_t)row * DKc + q * 8);
        *(uint4*)&Ks[row * SPADU + q * 4] =
            *(const uint4*)(Kb + (size_t)row * DKc + q * 8);
    }
    __syncthreads();

    float acc[4][4][4];
#pragma unroll
    for (int mt = 0; mt < 4; mt++)
#pragma unroll
        for (int nt = 0; nt < 4; nt++)
#pragma unroll
            for (int r = 0; r < 4; r++) acc[mt][nt][r] = 0.f;

#pragma unroll
    for (int ksu = 0; ksu < 32; ksu += 8) {
        uint32_t af[4][4], bf[4][2];
#pragma unroll
        for (int mt = 0; mt < 4; mt++) {
            int rb = wm + mt * 16 + g;
            af[mt][0] = Qs[rb * SPADU + ksu + t];
            af[mt][1] = Qs[(rb + 8) * SPADU + ksu + t];
            af[mt][2] = Qs[rb * SPADU + ksu + t + 4];
            af[mt][3] = Qs[(rb + 8) * SPADU + ksu + t + 4];
        }
#pragma unroll
        for (int nt = 0; nt < 4; nt++) {
            int cb = wn + nt * 8 + g;
            bf[nt][0] = Ks[cb * SPADU + ksu + t];
            bf[nt][1] = Ks[cb * SPADU + ksu + t + 4];
        }
#pragma unroll
        for (int mt = 0; mt < 4; mt++)
#pragma unroll
            for (int nt = 0; nt < 4; nt++)
                mma_f16(acc[mt][nt], af[mt], bf[nt]);
    }

    const bool diag = (kt == qt);
#pragma unroll
    for (int mt = 0; mt < 4; mt++) {
        int lr0 = wm + mt * 16 + g;
        int lr1 = lr0 + 8;
        int r0 = qt * 128 + lr0;
        int r1 = r0 + 8;
        float rs0 = 0.f, rs1 = 0.f;
#pragma unroll
        for (int nt = 0; nt < 4; nt++) {
            int c = kt * 128 + wn + nt * 8 + 2 * t;
            float e00 = __expf(acc[mt][nt][0] * 0.125f);
            float e01 = __expf(acc[mt][nt][1] * 0.125f);
            float e10 = __expf(acc[mt][nt][2] * 0.125f);
            float e11 = __expf(acc[mt][nt][3] * 0.125f);
            if (diag) {
                if (c > r0) e00 = 0.f;
                if (c + 1 > r0) e01 = 0.f;
                if (c > r1) e10 = 0.f;
                if (c + 1 > r1) e11 = 0.f;
            }
            rs0 += e00 + e01;
            rs1 += e10 + e11;
            *(float2*)(attn + ((size_t)bh * Sc + r0) * Sc + c) = make_float2(e00, e01);
            *(float2*)(attn + ((size_t)bh * Sc + r1) * Sc + c) = make_float2(e10, e11);
        }
        rs0 += __shfl_xor_sync(0xffffffffu, rs0, 1);
        rs0 += __shfl_xor_sync(0xffffffffu, rs0, 2);
        rs1 += __shfl_xor_sync(0xffffffffu, rs1, 1);
        rs1 += __shfl_xor_sync(0xffffffffu, rs1, 2);
        if (t == 0) {
            sp[lr0][w & 3] = rs0;
            sp[lr1][w & 3] = rs1;
        }
    }
    __syncthreads();
    if (tid < 128) {
        float s = sp[tid][0] + sp[tid][1] + sp[tid][2] + sp[tid][3];
        rsp[((size_t)bh * 8 + kt) * 1024 + qt * 128 + tid] = s;
    }
}

// ======================= context + softmax-normalize fusion ==================
// Reads unnormalized exp-P, normalizes by row sum (from g_rsp partials),
// WRITES normalized attn back to gmem, converts to half for PV MMA.
#define CPADU 36
#define CTX_SMEM ((128 * CPADU + 64 * CPADU) * 4)   // 27648 bytes

__global__ __launch_bounds__(256, 2) void context_mma(
    float* __restrict__ attn, const __half* __restrict__ V,
    __half* __restrict__ ctx, const float* __restrict__ rsp)
{
    const int qt = (int)gridDim.x - 1 - (int)blockIdx.x;  // longest-job-first
    const int bh = blockIdx.y;

    extern __shared__ uint32_t shc[];
    uint32_t* Ps = shc;                 // [128 q][CPADU]
    uint32_t* Vs = shc + 128 * CPADU;   // [64 d][CPADU]
    __shared__ float sinv[128];

    const int tid = threadIdx.x;
    const int lane = tid & 31;
    const int w = tid >> 5;
    const int g = lane >> 2, t = lane & 3;
    const int wm = (w >> 1) * 32;
    const int wn = (w & 1) * 32;

    const int nst = 2 * (qt + 1);

    // row inverse sums from partials (deterministic ascending-kt order)
    if (tid < 128) {
        float s = 0.f;
        for (int kt = 0; kt <= qt; kt++)
            s += rsp[((size_t)bh * 8 + kt) * 1024 + qt * 128 + tid];
        sinv[tid] = 1.f / s;
    }
    __syncthreads();

    float acc[2][4][4];
#pragma unroll
    for (int mt = 0; mt < 2; mt++)
#pragma unroll
        for (int nt = 0; nt < 4; nt++)
#pragma unroll
            for (int r = 0; r < 4; r++) acc[mt][nt][r] = 0.f;

    float* Pb = attn + ((size_t)bh * Sc + qt * 128) * Sc;
    const __half* Vb = V + (size_t)bh * Sc * DKc;

    float4 pp[8];
    uint2 pv0[2], pv1[2];

    // prefetch stage 0
#pragma unroll
    for (int i = 0; i < 8; i++) {
        int f4 = i * 256 + tid;
        int row = f4 >> 4, cc = (f4 & 15) << 2;
        pp[i] = *(const float4*)(Pb + (size_t)row * Sc + cc);
    }
#pragma unroll
    for (int j = 0; j < 2; j++) {
        int u = tid * 2 + j;
        int ku = u >> 4, dq = u & 15;
        pv0[j] = *(const uint2*)(Vb + (size_t)(2 * ku) * DKc + dq * 4);
        pv1[j] = *(const uint2*)(Vb + (size_t)(2 * ku + 1) * DKc + dq * 4);
    }
#pragma unroll
    for (int i = 0; i < 8; i++) {
        int f4 = i * 256 + tid;
        int row = f4 >> 4, cc = (f4 & 15) << 2;
        float inv = sinv[row];
        float4 v = make_float4(pp[i].x * inv, pp[i].y * inv,
                               pp[i].z * inv, pp[i].w * inv);
        *(float4*)(Pb + (size_t)row * Sc + cc) = v;   // normalized attn out
        Ps[row * CPADU + (cc >> 1)] = h2u(__float22half2_rn(make_float2(v.x, v.y)));
        Ps[row * CPADU + (cc >> 1) + 1] = h2u(__float22half2_rn(make_float2(v.z, v.w)));
    }
#pragma unroll
    for (int j = 0; j < 2; j++) {
        int u = tid * 2 + j;
        int ku = u >> 4, dq = u & 15;
        __half2 a0 = *reinterpret_cast<__half2*>(&pv0[j].x);
        __half2 a1 = *reinterpret_cast<__half2*>(&pv0[j].y);
        __half2 b0 = *reinterpret_cast<__half2*>(&pv1[j].x);
        __half2 b1 = *reinterpret_cast<__half2*>(&pv1[j].y);
        Vs[(dq * 4 + 0) * CPADU + ku] = h2u(__halves2half2(__low2half(a0), __low2half(b0)));
        Vs[(dq * 4 + 1) * CPADU + ku] = h2u(__halves2half2(__high2half(a0), __high2half(b0)));
        Vs[(dq * 4 + 2) * CPADU + ku] = h2u(__halves2half2(__low2half(a1), __low2half(b1)));
        Vs[(dq * 4 + 3) * CPADU + ku] = h2u(__halves2half2(__high2half(a1), __high2half(b1)));
    }
    __syncthreads();

    for (int st = 0; st < nst; st++) {
        if (st + 1 < nst) {
            const int kk = (st + 1) * 64;
#pragma unroll
            for (int i = 0; i < 8; i++) {
                int f4 = i * 256 + tid;
                int row = f4 >> 4, cc = (f4 & 15) << 2;
                pp[i] = *(const float4*)(Pb + (size_t)row * Sc + kk + cc);
            }
#pragma unroll
            for (int j = 0; j < 2; j++) {
                int u = tid * 2 + j;
                int ku = u >> 4, dq = u & 15;
                pv0[j] = *(const uint2*)(Vb + (size_t)(kk + 2 * ku) * DKc + dq * 4);
                pv1[j] = *(const uint2*)(Vb + (size_t)(kk + 2 * ku + 1) * DKc + dq * 4);
            }
        }

#pragma unroll
        for (int ksu = 0; ksu < 32; ksu += 8) {
            uint32_t af[2][4], bf[4][2];
#pragma unroll
            for (int mt = 0; mt < 2; mt++) {
                int rb = wm + mt * 16 + g;
                af[mt][0] = Ps[rb * CPADU + ksu + t];
                af[mt][1] = Ps[(rb + 8) * CPADU + ksu + t];
                af[mt][2] = Ps[rb * CPADU + ksu + t + 4];
                af[mt][3] = Ps[(rb + 8) * CPADU + ksu + t + 4];
            }
#pragma unroll
            for (int nt = 0; nt < 4; nt++) {
                int cb = wn + nt * 8 + g;
                bf[nt][0] = Vs[cb * CPADU + ksu + t];
                bf[nt][1] = Vs[cb * CPADU + ksu + t + 4];
            }
#pragma unroll
            for (int mt = 0; mt < 2; mt++)
#pragma unroll
                for (int nt = 0; nt < 4; nt++)
                    mma_f16(acc[mt][nt], af[mt], bf[nt]);
        }

        if (st + 1 < nst) {
            const int kk = (st + 1) * 64;
            __syncthreads();
#pragma unroll
            for (int i = 0; i < 8; i++) {
                int f4 = i * 256 + tid;
                int row = f4 >> 4, cc = (f4 & 15) << 2;
                float inv = sinv[row];
                float4 v = make_float4(pp[i].x * inv, pp[i].y * inv,
                                       pp[i].z * inv, pp[i].w * inv);
                *(float4*)(Pb + (size_t)row * Sc + kk + cc) = v;
                Ps[row * CPADU + (cc >> 1)] = h2u(__float22half2_rn(make_float2(v.x, v.y)));
                Ps[row * CPADU + (cc >> 1) + 1] = h2u(__float22half2_rn(make_float2(v.z, v.w)));
            }
#pragma unroll
            for (int j = 0; j < 2; j++) {
                int u = tid * 2 + j;
                int ku = u >> 4, dq = u & 15;
                __half2 a0 = *reinterpret_cast<__half2*>(&pv0[j].x);
                __half2 a1 = *reinterpret_cast<__half2*>(&pv0[j].y);
                __half2 b0 = *reinterpret_cast<__half2*>(&pv1[j].x);
                __half2 b1 = *reinterpret_cast<__half2*>(&pv1[j].y);
                Vs[(dq * 4 + 0) * CPADU + ku] = h2u(__halves2half2(__low2half(a0), __low2half(b0)));
                Vs[(dq * 4 + 1) * CPADU + ku] = h2u(__halves2half2(__high2half(a0), __high2half(b0)));
                Vs[(dq * 4 + 2) * CPADU + ku] = h2u(__halves2half2(__low2half(a1), __low2half(b1)));
                Vs[(dq * 4 + 3) * CPADU + ku] = h2u(__halves2half2(__high2half(a1), __high2half(b1)));
            }
            __syncthreads();
        }
    }

    const int b = bh >> 4;
    const int h = bh & 15;
#pragma unroll
    for (int mt = 0; mt < 2; mt++) {
        int q0 = qt * 128 + wm + mt * 16 + g;
        int q1 = q0 + 8;
#pragma unroll
        for (int nt = 0; nt < 4; nt++) {
            int c = wn + nt * 8 + 2 * t;
            __half2 v0 = __float22half2_rn(make_float2(acc[mt][nt][0], acc[mt][nt][1]));
            __half2 v1 = __float22half2_rn(make_float2(acc[mt][nt][2], acc[mt][nt][3]));
            *(__half2*)(ctx + ((size_t)b * Sc + q0) * Dc + h * 64 + c) = v0;
            *(__half2*)(ctx + ((size_t)b * Sc + q1) * Dc + h * 64 + c) = v1;
        }
    }
}

// ---------------- warp-per-row residual + LayerNorm -------------------------
__global__ __launch_bounds__(256) void addln_warp(
    const float* __restrict__ fc, const float* __restrict__ resid,
    float* __restrict__ out)
{
    const int wid = threadIdx.x >> 5, lane = threadIdx.x & 31;
    const int m = blockIdx.x * 8 + wid;

    __shared__ float xr[8][1024];
    const float* fp = fc + (size_t)m * Dc;
    const float* rp = resid + (size_t)m * Dc;

    float s = 0.f;
#pragma unroll
    for (int j4 = lane * 4; j4 < Dc; j4 += 128) {
        float4 a = *(const float4*)(fp + j4);
        float4 b = *(const float4*)(rp + j4);
        float4 x = make_float4(a.x + b.x, a.y + b.y, a.z + b.z, a.w + b.w);
        *(float4*)&xr[wid][j4] = x;
        s += x.x + x.y + x.z + x.w;
    }
#pragma unroll
    for (int o = 16; o; o >>= 1) s += __shfl_xor_sync(0xffffffffu, s, o);
    const float mu = s * (1.f / 1024.f);

    float ss = 0.f;
#pragma unroll
    for (int j4 = lane * 4; j4 < Dc; j4 += 128) {
        float4 x = *(const float4*)&xr[wid][j4];
        float dx = x.x - mu, dy = x.y - mu, dz = x.z - mu, dw = x.w - mu;
        ss += dx * dx + dy * dy + dz * dz + dw * dw;
    }
#pragma unroll
    for (int o = 16; o; o >>= 1) ss += __shfl_xor_sync(0xffffffffu, ss, o);
    const float inv = rsqrtf(ss * (1.f / 1024.f) + 1e-5f);

    float* op = out + (size_t)m * Dc;
#pragma unroll
    for (int j4 = lane * 4; j4 < Dc; j4 += 128) {
        float4 x = *(const float4*)&xr[wid][j4];
        *(float4*)(op + j4) = make_float4((x.x - mu) * inv, (x.y - mu) * inv,
                                          (x.z - mu) * inv, (x.w - mu) * inv);
    }
}

// ---------------- launch -----------------------------------------------------
extern "C" void kernel_launch(void* const* d_in, const int* in_sizes, int n_in,
                              void* d_out, int out_size)
{
    const float* inQ = (const float*)d_in[0];
    const float* inK = (const float*)d_in[1];
    const float* inV = (const float*)d_in[2];
    // d_in[3] = causal mask (fixed triu) — implemented analytically
    const float* Wq = (const float*)d_in[4];
    const float* Wk = (const float*)d_in[5];
    const float* Wv = (const float*)d_in[6];
    const float* Wfc = (const float*)d_in[7];

    float* out = (float*)d_out;                       // [B,S,D]
    float* attn = out + (size_t)Bc * Sc * Dc;         // [B,H,S,S]

    __half *pA16, *pQ16, *pK16, *pV16, *pctx16, *pWt16;
    float *pfc, *prsp;
    cudaGetSymbolAddress((void**)&pA16, g_A16);
    cudaGetSymbolAddress((void**)&pQ16, g_Q16);
    cudaGetSymbolAddress((void**)&pK16, g_K16);
    cudaGetSymbolAddress((void**)&pV16, g_V16);
    cudaGetSymbolAddress((void**)&pctx16, g_ctx16);
    cudaGetSymbolAddress((void**)&pfc, g_fc);
    cudaGetSymbolAddress((void**)&pWt16, g_Wt16);
    cudaGetSymbolAddress((void**)&prsp, g_rsp);

    cudaFuncSetAttribute(gemm16,
                         cudaFuncAttributeMaxDynamicSharedMemorySize, GEMM_SMEM);
    cudaFuncSetAttribute(scores_mma,
                         cudaFuncAttributeMaxDynamicSharedMemorySize, SCORES_SMEM);
    cudaFuncSetAttribute(context_mma,
                         cudaFuncAttributeMaxDynamicSharedMemorySize, CTX_SMEM);

    const size_t WSZ = 1024u * 1024u;
    convert3<<<dim3(4096, 3), 256>>>(inQ, inK, inV, pA16);
    transpose_kernel<<<dim3(32, 32, 4), 256>>>(Wq, Wk, Wv, Wfc, pWt16);

    // batched Q,K,V projections, fp16 headed outputs
    gemm16<<<dim3(8, 64, 3), 256, GEMM_SMEM>>>(
        pA16, pWt16, pQ16, pK16, pV16, nullptr, 1);

    scores_mma<<<dim3(8, 8, Bc * Hc), 256, SCORES_SMEM>>>(
        pQ16, pK16, attn, prsp);
    context_mma<<<dim3(8, Bc * Hc), 256, CTX_SMEM>>>(
        attn, pV16, pctx16, prsp);

    // FC GEMM: A = ctx fp16 (flat), weight slice 3, fp32 flat output
    gemm16<<<dim3(8, 64, 1), 256, GEMM_SMEM>>>(
        pctx16, pWt16 + 3 * WSZ, nullptr, nullptr, nullptr, pfc, 0);

    addln_warp<<<Bc * Sc / 8, 256>>>(pfc, inQ, out);
}